// round 1
// baseline (speedup 1.0000x reference)
#include <cuda_runtime.h>
#include <cuda_bf16.h>

// Problem dims
#define BATCH  64
#define SDIM   4096
#define DDIM   256
#define SCHUNK 512
#define NCHUNK (SDIM / SCHUNK)          // 8
#define NBLK   (BATCH * NCHUNK)         // 512 partial blocks

// Scratch for cross-CTA partials (no allocation allowed -> device globals)
__device__ float g_acc[NBLK * DDIM];    // 512 KB
__device__ float g_sum[NBLK];

// ---------------------------------------------------------------------------
// Pass 1: for each (batch, s-chunk) CTA compute
//   partial_acc[d] = sum_{s in chunk} exp(tanh(m[s]·Wm + c_b)) * m[s][d]
//   partial_sum    = sum_{s in chunk} exp(tanh(...))
// gi = tanh(.) in [-1,1] => exp never overflows, no max-subtraction needed,
// so softmax folds into a SINGLE pass over memory (268 MB read once).
// ---------------------------------------------------------------------------
__global__ __launch_bounds__(256, 3)
void att_pass1(const float* __restrict__ memory,
               const float* __restrict__ aspect,
               const float* __restrict__ W,
               const float* __restrict__ bias)
{
    __shared__ float red[8];
    __shared__ float sacc[DDIM];
    __shared__ float ssum;
    __shared__ float sc;

    const int tid  = threadIdx.x;
    const int lane = tid & 31;
    const int warp = tid >> 5;
    const int blk  = blockIdx.x;
    const int b    = blk >> 3;       // / NCHUNK
    const int chnk = blk & (NCHUNK - 1);

    // ---- c_b = aspect[b]·Wa + bias (cheap, per-CTA redundant) ----
    float v = aspect[b * DDIM + tid] * W[DDIM + tid];
    #pragma unroll
    for (int o = 16; o; o >>= 1) v += __shfl_xor_sync(0xffffffffu, v, o);
    if (lane == 0) red[warp] = v;
    sacc[tid] = 0.f;
    if (tid == 0) ssum = 0.f;
    __syncthreads();
    if (tid == 0) {
        float c = bias[0];
        #pragma unroll
        for (int i = 0; i < 8; i++) c += red[i];
        sc = c;
    }
    __syncthreads();
    const float cb = sc;

    // ---- Wm slice held in registers: lane covers d = 4*lane..4*lane+3 and 128+4*lane.. ----
    const float4 wm0 = *reinterpret_cast<const float4*>(W + 4 * lane);
    const float4 wm1 = *reinterpret_cast<const float4*>(W + 128 + 4 * lane);

    float4 a0 = make_float4(0.f, 0.f, 0.f, 0.f);
    float4 a1 = make_float4(0.f, 0.f, 0.f, 0.f);
    float  sw = 0.f;

    const float* base = memory + ((long)b * SDIM + (long)chnk * SCHUNK) * DDIM;

    // warp-per-row; 64 rows per warp; unroll for independent shuffle chains / MLP
    #pragma unroll 4
    for (int r = warp; r < SCHUNK; r += 8) {
        const float4* row = reinterpret_cast<const float4*>(base + (long)r * DDIM);
        const float4 m0 = row[lane];
        const float4 m1 = row[32 + lane];

        float d = m0.x * wm0.x + m0.y * wm0.y + m0.z * wm0.z + m0.w * wm0.w
                + m1.x * wm1.x + m1.y * wm1.y + m1.z * wm1.z + m1.w * wm1.w;
        #pragma unroll
        for (int o = 16; o; o >>= 1) d += __shfl_xor_sync(0xffffffffu, d, o);

        const float gi = tanhf(d + cb);
        const float w  = __expf(gi);

        a0.x += w * m0.x; a0.y += w * m0.y; a0.z += w * m0.z; a0.w += w * m0.w;
        a1.x += w * m1.x; a1.y += w * m1.y; a1.z += w * m1.z; a1.w += w * m1.w;
        if (lane == 0) sw += w;
    }

    // ---- combine 8 warps via smem atomics (2048 spread-address ATOMS, trivial) ----
    atomicAdd(&sacc[4 * lane + 0], a0.x);
    atomicAdd(&sacc[4 * lane + 1], a0.y);
    atomicAdd(&sacc[4 * lane + 2], a0.z);
    atomicAdd(&sacc[4 * lane + 3], a0.w);
    atomicAdd(&sacc[128 + 4 * lane + 0], a1.x);
    atomicAdd(&sacc[128 + 4 * lane + 1], a1.y);
    atomicAdd(&sacc[128 + 4 * lane + 2], a1.z);
    atomicAdd(&sacc[128 + 4 * lane + 3], a1.w);
    if (lane == 0) atomicAdd(&ssum, sw);
    __syncthreads();

    g_acc[blk * DDIM + tid] = sacc[tid];
    if (tid == 0) g_sum[blk] = ssum;
}

// ---------------------------------------------------------------------------
// Pass 2: out[b][d] = (sum_c acc[b,c,d]) / (sum_c sum[b,c])
// ---------------------------------------------------------------------------
__global__ __launch_bounds__(256)
void att_pass2(float* __restrict__ out)
{
    const int b   = blockIdx.x;
    const int tid = threadIdx.x;
    float acc = 0.f, s = 0.f;
    #pragma unroll
    for (int c = 0; c < NCHUNK; c++) {
        acc += g_acc[(b * NCHUNK + c) * DDIM + tid];
        s   += g_sum[b * NCHUNK + c];
    }
    out[b * DDIM + tid] = acc / s;
}

extern "C" void kernel_launch(void* const* d_in, const int* in_sizes, int n_in,
                              void* d_out, int out_size)
{
    // Robust input mapping by element counts:
    //   memory: B*S*D = 67108864, aspect: B*D = 16384, W: 2*D = 512, b: 1
    const float *aspect = nullptr, *memory = nullptr, *W = nullptr, *bias = nullptr;
    for (int i = 0; i < n_in; i++) {
        const long n = (long)in_sizes[i];
        const float* p = (const float*)d_in[i];
        if      (n == (long)BATCH * SDIM * DDIM) memory = p;
        else if (n == (long)BATCH * DDIM)        aspect = p;
        else if (n == 2 * DDIM)                  W      = p;
        else if (n == 1)                         bias   = p;
    }

    att_pass1<<<NBLK, 256>>>(memory, aspect, W, bias);
    att_pass2<<<BATCH, 256>>>((float*)d_out);
}

// round 3
// speedup vs baseline: 1.2486x; 1.2486x over previous
#include <cuda_runtime.h>
#include <cuda_bf16.h>

// Problem dims
#define BATCH  64
#define SDIM   4096
#define DDIM   256
#define SCHUNK 512
#define NCHUNK (SDIM / SCHUNK)          // 8
#define NBLK   (BATCH * NCHUNK)         // 512 CTAs — single wave at occ 4 (592 slots)

// Scratch for cross-CTA partials (no allocation allowed -> device globals)
__device__ float g_acc[NBLK * DDIM];    // 512 KB
__device__ float g_sum[NBLK];
__device__ int   g_cnt[BATCH];          // zero-init; re-armed by finalizer each run

// sm_103a has no redux.sync.f32 — classic butterfly
__device__ __forceinline__ float warp_sum(float v) {
    #pragma unroll
    for (int o = 16; o; o >>= 1) v += __shfl_xor_sync(0xffffffffu, v, o);
    return v;
}

// ---------------------------------------------------------------------------
// Fused kernel: per (batch, s-chunk) CTA computes
//   partial_acc[d] = sum_{s in chunk} exp(tanh(m[s]·Wm + c_b)) * m[s][d]
//   partial_sum    = sum_{s in chunk} exp(tanh(...))
// gi = tanh(.) in [-1,1] => exp never overflows => no max-subtraction,
// softmax folds into ONE pass over memory (268 MB read exactly once).
// Last CTA per batch (threadfence-reduction pattern) writes the output —
// no second kernel.
// ---------------------------------------------------------------------------
__global__ __launch_bounds__(256, 4)
void att_fused(const float* __restrict__ memory,
               const float* __restrict__ aspect,
               const float* __restrict__ W,
               const float* __restrict__ bias,
               float* __restrict__ out)
{
    __shared__ float sacc[DDIM];
    __shared__ float ssum;
    __shared__ float sc;
    __shared__ int   s_old;

    const int tid  = threadIdx.x;
    const int lane = tid & 31;
    const int warp = tid >> 5;
    const int blk  = blockIdx.x;
    const int b    = blk >> 3;       // / NCHUNK
    const int chnk = blk & (NCHUNK - 1);

    // ---- c_b = aspect[b]·Wa + bias (cheap, per-CTA redundant) ----
    {
        float v = warp_sum(aspect[b * DDIM + tid] * W[DDIM + tid]);
        if (tid == 0) { ssum = 0.f; sc = bias[0]; }
        sacc[tid] = 0.f;
        __syncthreads();
        if (lane == 0) atomicAdd(&sc, v);
        __syncthreads();
    }
    const float cb = sc;

    // ---- Wm slice in registers: lane covers d = 4*lane.. and 128+4*lane.. ----
    const float4 wm0 = *reinterpret_cast<const float4*>(W + 4 * lane);
    const float4 wm1 = *reinterpret_cast<const float4*>(W + 128 + 4 * lane);

    float4 a0 = make_float4(0.f, 0.f, 0.f, 0.f);
    float4 a1 = make_float4(0.f, 0.f, 0.f, 0.f);
    float  sw = 0.f;

    const float* base = memory + ((long)b * SDIM + (long)chnk * SCHUNK) * DDIM;

    // warp-per-row; 64 rows per warp; unroll 4 -> 8 LDG.128 + 4 independent
    // shuffle chains in flight per warp
    #pragma unroll 4
    for (int r = warp; r < SCHUNK; r += 8) {
        const float4* row = reinterpret_cast<const float4*>(base + (long)r * DDIM);
        const float4 m0 = row[lane];
        const float4 m1 = row[32 + lane];

        float d = m0.x * wm0.x + m0.y * wm0.y + m0.z * wm0.z + m0.w * wm0.w
                + m1.x * wm1.x + m1.y * wm1.y + m1.z * wm1.z + m1.w * wm1.w;
        d = warp_sum(d);

        const float gi = tanhf(d + cb);
        const float w  = __expf(gi);

        a0.x += w * m0.x; a0.y += w * m0.y; a0.z += w * m0.z; a0.w += w * m0.w;
        a1.x += w * m1.x; a1.y += w * m1.y; a1.z += w * m1.z; a1.w += w * m1.w;
        if (lane == 0) sw += w;
    }

    // ---- combine 8 warps via smem atomics (spread addresses, cheap) ----
    atomicAdd(&sacc[4 * lane + 0], a0.x);
    atomicAdd(&sacc[4 * lane + 1], a0.y);
    atomicAdd(&sacc[4 * lane + 2], a0.z);
    atomicAdd(&sacc[4 * lane + 3], a0.w);
    atomicAdd(&sacc[128 + 4 * lane + 0], a1.x);
    atomicAdd(&sacc[128 + 4 * lane + 1], a1.y);
    atomicAdd(&sacc[128 + 4 * lane + 2], a1.z);
    atomicAdd(&sacc[128 + 4 * lane + 3], a1.w);
    if (lane == 0) atomicAdd(&ssum, sw);
    __syncthreads();

    g_acc[blk * DDIM + tid] = sacc[tid];
    if (tid == 0) g_sum[blk] = ssum;
    __syncthreads();

    // ---- last-CTA-per-batch finalize (threadfence-reduction pattern) ----
    if (tid == 0) {
        __threadfence();
        s_old = atomicAdd(&g_cnt[b], 1);
    }
    __syncthreads();
    if (s_old == NCHUNK - 1) {
        __threadfence();                       // acquire siblings' partials
        float acc = 0.f, s = 0.f;
        #pragma unroll
        for (int c = 0; c < NCHUNK; c++) {
            acc += g_acc[(b * NCHUNK + c) * DDIM + tid];
            s   += g_sum[b * NCHUNK + c];
        }
        out[b * DDIM + tid] = acc / s;
        __syncthreads();
        if (tid == 0) g_cnt[b] = 0;            // re-arm for next graph replay
    }
}

extern "C" void kernel_launch(void* const* d_in, const int* in_sizes, int n_in,
                              void* d_out, int out_size)
{
    // Map inputs by element count:
    //   memory: B*S*D = 67108864, aspect: B*D = 16384, W: 2*D = 512, b: 1
    const float *aspect = nullptr, *memory = nullptr, *W = nullptr, *bias = nullptr;
    for (int i = 0; i < n_in; i++) {
        const long n = (long)in_sizes[i];
        const float* p = (const float*)d_in[i];
        if      (n == (long)BATCH * SDIM * DDIM) memory = p;
        else if (n == (long)BATCH * DDIM)        aspect = p;
        else if (n == 2 * DDIM)                  W      = p;
        else if (n == 1)                         bias   = p;
    }

    att_fused<<<NBLK, 256>>>(memory, aspect, W, bias, (float*)d_out);
}

// round 4
// speedup vs baseline: 1.3371x; 1.0709x over previous
#include <cuda_runtime.h>
#include <cuda_bf16.h>

// Problem dims
#define BATCH  64
#define SDIM   4096
#define DDIM   256
#define SCHUNK 512
#define NCHUNK (SDIM / SCHUNK)          // 8
#define NBLK   (BATCH * NCHUNK)         // 512 CTAs — single wave at occ 4

// Scratch for cross-CTA partials (no allocation allowed -> device globals)
__device__ float g_acc[NBLK * DDIM];    // 512 KB
__device__ float g_sum[NBLK];
__device__ int   g_cnt[BATCH];          // zero-init; re-armed by finalizer each run

// sm_103a has no redux.sync.f32 — classic butterfly
__device__ __forceinline__ float warp_sum(float v) {
    #pragma unroll
    for (int o = 16; o; o >>= 1) v += __shfl_xor_sync(0xffffffffu, v, o);
    return v;
}

__device__ __forceinline__ float dot8(const float4& m0, const float4& m1,
                                      const float4& w0, const float4& w1) {
    return m0.x * w0.x + m0.y * w0.y + m0.z * w0.z + m0.w * w0.w
         + m1.x * w1.x + m1.y * w1.y + m1.z * w1.z + m1.w * w1.w;
}

// ---------------------------------------------------------------------------
// Single pass over memory (268 MB read exactly once):
//   gi = tanh(m·Wm + c_b) in [-1,1]  =>  exp never overflows  =>  softmax
//   needs no running max; accumulate exp(gi)*m and exp(gi) directly.
// Software-pipelined: next 2 rows' loads issue BEFORE the current rows'
// shuffle/tanh/exp chain, keeping LDGs in flight during the ~200cyc chain.
// Last CTA per batch finalizes the output (threadfence-reduction pattern).
// ---------------------------------------------------------------------------
__global__ __launch_bounds__(256, 4)
void att_fused(const float* __restrict__ memory,
               const float* __restrict__ aspect,
               const float* __restrict__ W,
               const float* __restrict__ bias,
               float* __restrict__ out)
{
    __shared__ float sacc[DDIM];
    __shared__ float ssum;
    __shared__ float sc;
    __shared__ int   s_old;

    const int tid  = threadIdx.x;
    const int lane = tid & 31;
    const int warp = tid >> 5;
    const int blk  = blockIdx.x;
    const int b    = blk >> 3;       // / NCHUNK
    const int chnk = blk & (NCHUNK - 1);

    // ---- c_b = aspect[b]·Wa + bias ----
    {
        float v = warp_sum(aspect[b * DDIM + tid] * W[DDIM + tid]);
        if (tid == 0) { ssum = 0.f; sc = bias[0]; }
        sacc[tid] = 0.f;
        __syncthreads();
        if (lane == 0) atomicAdd(&sc, v);
        __syncthreads();
    }
    const float cb = sc;

    // ---- Wm slice in registers: lane covers d = 4*lane.. and 128+4*lane.. ----
    const float4 wm0 = *reinterpret_cast<const float4*>(W + 4 * lane);
    const float4 wm1 = *reinterpret_cast<const float4*>(W + 128 + 4 * lane);

    float4 a0 = make_float4(0.f, 0.f, 0.f, 0.f);
    float4 a1 = make_float4(0.f, 0.f, 0.f, 0.f);
    float  sw = 0.f;

    const float4* base = reinterpret_cast<const float4*>(
        memory + ((long)b * SDIM + (long)chnk * SCHUNK) * DDIM);
    // row r occupies float4s [r*64, r*64+64); this warp does r = warp + 8*i
    const float4* p = base + (long)warp * 64;
    const long rstep = 8 * 64;                 // 8 rows ahead per i

    // prologue: rows i=0,1
    float4 c00 = p[lane],             c01 = p[32 + lane];
    float4 c10 = p[rstep + lane],     c11 = p[rstep + 32 + lane];

    #pragma unroll 2
    for (int i = 0; i < 64; i += 2) {
        // ---- prefetch rows i+2, i+3 (guarded; dead on last iter) ----
        float4 n00, n01, n10, n11;
        if (i + 2 < 64) {
            const float4* q = p + (long)(i + 2) * rstep;
            n00 = q[lane];          n01 = q[32 + lane];
            n10 = q[rstep + lane];  n11 = q[rstep + 32 + lane];
        }

        // ---- two independent dot/reduce/activation chains ----
        float d0 = warp_sum(dot8(c00, c01, wm0, wm1));
        float d1 = warp_sum(dot8(c10, c11, wm0, wm1));
        const float w0 = __expf(tanhf(d0 + cb));
        const float w1 = __expf(tanhf(d1 + cb));

        a0.x += w0 * c00.x + w1 * c10.x;  a0.y += w0 * c00.y + w1 * c10.y;
        a0.z += w0 * c00.z + w1 * c10.z;  a0.w += w0 * c00.w + w1 * c10.w;
        a1.x += w0 * c01.x + w1 * c11.x;  a1.y += w0 * c01.y + w1 * c11.y;
        a1.z += w0 * c01.z + w1 * c11.z;  a1.w += w0 * c01.w + w1 * c11.w;
        sw   += w0 + w1;                   // w uniform across lanes post-butterfly

        c00 = n00; c01 = n01; c10 = n10; c11 = n11;
    }

    // ---- combine 8 warps via smem atomics (spread addresses, cheap) ----
    atomicAdd(&sacc[4 * lane + 0], a0.x);
    atomicAdd(&sacc[4 * lane + 1], a0.y);
    atomicAdd(&sacc[4 * lane + 2], a0.z);
    atomicAdd(&sacc[4 * lane + 3], a0.w);
    atomicAdd(&sacc[128 + 4 * lane + 0], a1.x);
    atomicAdd(&sacc[128 + 4 * lane + 1], a1.y);
    atomicAdd(&sacc[128 + 4 * lane + 2], a1.z);
    atomicAdd(&sacc[128 + 4 * lane + 3], a1.w);
    if (lane == 0) atomicAdd(&ssum, sw);
    __syncthreads();

    g_acc[blk * DDIM + tid] = sacc[tid];
    if (tid == 0) g_sum[blk] = ssum;
    __syncthreads();

    // ---- last-CTA-per-batch finalize ----
    if (tid == 0) {
        __threadfence();
        s_old = atomicAdd(&g_cnt[b], 1);
    }
    __syncthreads();
    if (s_old == NCHUNK - 1) {
        __threadfence();                       // acquire siblings' partials
        float acc = 0.f, s = 0.f;
        #pragma unroll
        for (int c = 0; c < NCHUNK; c++) {
            acc += g_acc[(b * NCHUNK + c) * DDIM + tid];
            s   += g_sum[b * NCHUNK + c];
        }
        out[b * DDIM + tid] = acc / s;
        __syncthreads();
        if (tid == 0) g_cnt[b] = 0;            // re-arm for next graph replay
    }
}

extern "C" void kernel_launch(void* const* d_in, const int* in_sizes, int n_in,
                              void* d_out, int out_size)
{
    // Map inputs by element count:
    //   memory: B*S*D = 67108864, aspect: B*D = 16384, W: 2*D = 512, b: 1
    const float *aspect = nullptr, *memory = nullptr, *W = nullptr, *bias = nullptr;
    for (int i = 0; i < n_in; i++) {
        const long n = (long)in_sizes[i];
        const float* p = (const float*)d_in[i];
        if      (n == (long)BATCH * SDIM * DDIM) memory = p;
        else if (n == (long)BATCH * DDIM)        aspect = p;
        else if (n == 2 * DDIM)                  W      = p;
        else if (n == 1)                         bias   = p;
    }

    att_fused<<<NBLK, 256>>>(memory, aspect, W, bias, (float*)d_out);
}